// round 16
// baseline (speedup 1.0000x reference)
#include <cuda_runtime.h>
#include <math.h>

#define LS 48
#define LTm1 47
#define NB 64      // batch
#define E 512
#define H 512
#define VT 32000
#define NROWS 3008      // 47*64 decoder (step,batch) rows
#define NROWS_PAD 3072  // padded to multiple of 128
#define NCHUNK 250      // 32000/128
#define PADK 20         // smem row pad, G128 kernels (16 data + 4)
#define PADK2 36        // smem row pad, PIPE kernels (32 data + 4)
#define G128_STAGE (128 * PADK)            // floats per stage per operand
#define G128_DSMEM (4 * G128_STAGE * 2 * 4) // bytes: 4 stages x (A+B) x 4B = 81920

// ---------------- device scratch (static, allowed) ----------------
__device__ float g_zero[NB * H];
__device__ float g_embs_src[LS * NB * E];
__device__ float g_embs_tgt[NROWS_PAD * E];
__device__ float g_Xf[LS * NB * 2048];
__device__ float g_Xb[LS * NB * 2048];
__device__ float g_Gd[NROWS_PAD * 2048];
__device__ float g_hs[LS * NB * 1024];    // [t][b][1024] fwd||bwd
__device__ float g_hsp[LS * NB * 1024];   // hs_proj [l][b][1024]
__device__ float g_cf[NB * H];
__device__ float g_cb[NB * H];
__device__ float g_cd[NB * H];
__device__ float g_od[NB * H];
__device__ float g_q[NB * 1024];
__device__ float g_ctx[NB * 1024];
__device__ float g_H[NROWS_PAD * H];      // decoder h history
__device__ float g_tgt_logit[NROWS];
__device__ float g_maskv[NROWS];
__device__ float g_partial[NROWS_PAD * NCHUNK];
__device__ float g_blk[24];
// slot flags: one per producer block, monotonic step values; reset by k_prep
__device__ unsigned g_sE[256], g_sH[128], g_sQ[64], g_sC[64], g_sO[32];

__device__ __forceinline__ float sigm(float x) { return 1.f / (1.f + __expf(-x)); }

__device__ __forceinline__ float ftanh(float x) {
    float y;
    asm("tanh.approx.f32 %0, %1;" : "=f"(y) : "f"(x));
    return y;
}

// fast exp on the FMA pipe
__device__ __forceinline__ float fexp(float x) {
    float y = x * 1.44269504f;
    float fl = floorf(y);
    float f = y - fl;
    float p = fmaf(f, 0.0013333558f, 0.0096181291f);
    p = fmaf(f, p, 0.055504109f);
    p = fmaf(f, p, 0.24022651f);
    p = fmaf(f, p, 0.69314718f);
    p = fmaf(f, p, 1.0f);
    int e = (int)fl;
    return p * __int_as_float((e + 127) << 23);
}

__device__ __forceinline__ void mma_tf32(float* c, unsigned a0, unsigned a1, unsigned a2,
                                         unsigned a3, unsigned b0, unsigned b1) {
    asm volatile(
        "mma.sync.aligned.m16n8k8.row.col.f32.tf32.tf32.f32 "
        "{%0,%1,%2,%3},{%4,%5,%6,%7},{%8,%9},{%0,%1,%2,%3};"
        : "+f"(c[0]), "+f"(c[1]), "+f"(c[2]), "+f"(c[3])
        : "r"(a0), "r"(a1), "r"(a2), "r"(a3), "r"(b0), "r"(b1));
}

__device__ __forceinline__ void ldsm4(unsigned& r0, unsigned& r1, unsigned& r2, unsigned& r3,
                                      unsigned addr) {
    asm volatile("ldmatrix.sync.aligned.m8n8.x4.shared.b16 {%0,%1,%2,%3}, [%4];"
                 : "=r"(r0), "=r"(r1), "=r"(r2), "=r"(r3) : "r"(addr));
}
__device__ __forceinline__ void ldsm2(unsigned& r0, unsigned& r1, unsigned addr) {
    asm volatile("ldmatrix.sync.aligned.m8n8.x2.shared.b16 {%0,%1}, [%2];"
                 : "=r"(r0), "=r"(r1) : "r"(addr));
}

__device__ __forceinline__ void cpa16(unsigned dst, const void* src) {
    asm volatile("cp.async.ca.shared.global [%0], [%1], 16;" :: "r"(dst), "l"(src) : "memory");
}
__device__ __forceinline__ void cpa16cg(unsigned dst, const void* src) {
    asm volatile("cp.async.cg.shared.global [%0], [%1], 16;" :: "r"(dst), "l"(src) : "memory");
}
__device__ __forceinline__ void cpa4(unsigned dst, const void* src) {
    asm volatile("cp.async.ca.shared.global [%0], [%1], 4;" :: "r"(dst), "l"(src) : "memory");
}
#define CP_COMMIT() asm volatile("cp.async.commit_group;" ::: "memory")
#define CP_WAIT2()  asm volatile("cp.async.wait_group 2;" ::: "memory")

__device__ __forceinline__ unsigned ldcg_u32(const unsigned* p) {
    unsigned v;
    asm volatile("ld.global.cg.u32 %0, [%1];" : "=r"(v) : "l"(p));
    return v;
}
__device__ __forceinline__ float ldcg_f32(const float* p) {
    float v;
    asm volatile("ld.global.cg.f32 %0, [%1];" : "=f"(v) : "l"(p));
    return v;
}
__device__ __forceinline__ void st_rel(unsigned* p, unsigned v) {
    asm volatile("st.global.cg.u32 [%0], %1;" :: "l"(p), "r"(v) : "memory");
}

#define ARRIVE_SLOT(ARR, IDX, V)                                                \
    { __threadfence(); __syncthreads(); if (tid == 0) st_rel(&ARR[IDX], (V)); }
#define WAIT_SLOTS(ARR, CNT, TGT)                                               \
    { if (tid < (CNT)) { while (ldcg_u32(&ARR[tid]) < (TGT)) {} }               \
      __syncthreads(); }

// ---------------- prep: init states + slots + both gathers ----------------
__global__ void k_prep(const int* __restrict__ xs, const int* __restrict__ ts,
                       const float* __restrict__ src_emb, const float* __restrict__ tgt_emb) {
    int i = blockIdx.x * blockDim.x + threadIdx.x;
    int stride = gridDim.x * blockDim.x;
    if (i < 256) {
        g_sE[i] = 0;
        if (i < 128) g_sH[i] = 0;
        if (i < 64) { g_sQ[i] = 0; g_sC[i] = 0; }
        if (i < 32) g_sO[i] = 0;
    }
    int n = NB * H;
    for (int j = i; j < n; j += stride) {
        g_zero[j] = 0.f; g_cf[j] = 0.f; g_cb[j] = 0.f;
        g_cd[j] = 0.f; g_od[j] = 0.f;
        g_H[NROWS * H + j] = 0.f;
        g_embs_tgt[NROWS * E + j] = 0.f;
    }
    const float4* es = (const float4*)src_emb;
    const float4* et = (const float4*)tgt_emb;
    float4* os = (float4*)g_embs_src;
    float4* ot = (float4*)g_embs_tgt;
    int n4s = LS * NB * (E / 4);
    for (int j = i; j < n4s; j += stride) {
        int r = j >> 7, c = j & 127;
        os[j] = es[(size_t)xs[r] * 128 + c];
    }
    int n4t = LTm1 * NB * (E / 4);
    for (int j = i; j < n4t; j += stride) {
        int r = j >> 7, c = j & 127;
        ot[j] = et[(size_t)ts[r] * 128 + c];
    }
}

// ============================================================================
// 128x128 tf32 GEMM mainloop — 4-stage cp.async, ONE sync per stage,
// dynamic smem, row-major [m][PADK], ldmatrix fragment loads (raw fp32 bits).
// ============================================================================

#define G128_DECL()                                                             \
    extern __shared__ __align__(16) float dsm[];                                \
    int tid = threadIdx.x, lane = tid & 31, wid = tid >> 5;                     \
    int wm = wid & 3, wn = wid >> 2;                                            \
    int mo = wm * 32, no = wn * 64;                                             \
    int r0 = tid >> 2, q0 = tid & 3;                                            \
    int lrow8 = (lane & 7) + (lane & 8);                                        \
    int lcol4 = (lane >> 4) << 2;                                               \
    int brow = (lane & 7) + ((lane >> 4) << 3);                                 \
    int bcol4 = ((lane >> 3) & 1) << 2;                                         \
    unsigned sA = (unsigned)__cvta_generic_to_shared(&dsm[0]);                  \
    unsigned sB = sA + 4u * G128_STAGE * 4u;                                    \
    float c[2][8][4];                                                           \
    _Pragma("unroll")                                                           \
    for (int mt = 0; mt < 2; mt++)                                              \
        _Pragma("unroll")                                                       \
        for (int nt = 0; nt < 8; nt++)                                          \
            _Pragma("unroll")                                                   \
            for (int j = 0; j < 4; j++) c[mt][nt][j] = 0.f;

#define G128_ISSUE(S, BUF)                                                      \
    {                                                                           \
        cpa16(sA + ((BUF) * G128_STAGE + r0 * PADK + q0 * 4) * 4,               \
              &Ab[(size_t)r0 * lda + (S) * 16 + q0 * 4]);                       \
        cpa16(sA + ((BUF) * G128_STAGE + (r0 + 64) * PADK + q0 * 4) * 4,        \
              &Ab[(size_t)(r0 + 64) * lda + (S) * 16 + q0 * 4]);                \
        cpa16(sB + ((BUF) * G128_STAGE + r0 * PADK + q0 * 4) * 4,               \
              &Wb[(size_t)r0 * ldw + (S) * 16 + q0 * 4]);                       \
        cpa16(sB + ((BUF) * G128_STAGE + (r0 + 64) * PADK + q0 * 4) * 4,        \
              &Wb[(size_t)(r0 + 64) * ldw + (S) * 16 + q0 * 4]);                \
    }

#define G128_COMPUTE(BUF)                                                       \
    _Pragma("unroll")                                                           \
    for (int ks = 0; ks < 16; ks += 8) {                                        \
        unsigned a[2][4];                                                       \
        _Pragma("unroll")                                                       \
        for (int mt = 0; mt < 2; mt++) {                                        \
            unsigned ad = sA + ((BUF) * G128_STAGE +                            \
                                (mo + mt * 16 + lrow8) * PADK + ks + lcol4) * 4;\
            ldsm4(a[mt][0], a[mt][1], a[mt][2], a[mt][3], ad);                  \
        }                                                                       \
        _Pragma("unroll")                                                       \
        for (int np = 0; np < 4; np++) {                                        \
            unsigned b0, b1, b2, b3;                                            \
            unsigned bd = sB + ((BUF) * G128_STAGE +                            \
                                (no + np * 16 + brow) * PADK + ks + bcol4) * 4; \
            ldsm4(b0, b1, b2, b3, bd);                                          \
            mma_tf32(c[0][np * 2], a[0][0], a[0][1], a[0][2], a[0][3], b0, b1); \
            mma_tf32(c[1][np * 2], a[1][0], a[1][1], a[1][2], a[1][3], b0, b1); \
            mma_tf32(c[0][np * 2 + 1], a[0][0], a[0][1], a[0][2], a[0][3], b2, b3); \
            mma_tf32(c[1][np * 2 + 1], a[1][0], a[1][1], a[1][2], a[1][3], b2, b3); \
        }                                                                       \
    }

#define G128_RUN(NS)                                                            \
    G128_ISSUE(0, 0); CP_COMMIT();                                              \
    G128_ISSUE(1, 1); CP_COMMIT();                                              \
    G128_ISSUE(2, 2); CP_COMMIT();                                              \
    for (int s = 0; s < (NS); s++) {                                            \
        CP_WAIT2();                                                             \
        __syncthreads();                                                        \
        if (s + 3 < (NS)) G128_ISSUE(s + 3, (s + 3) & 3);                       \
        CP_COMMIT();                                                            \
        G128_COMPUTE(s & 3);                                                    \
    }                                                                           \
    __syncthreads();

// ---------------- fused precompute GEMMs: 3 modes in one launch (grid.z) ----------------
__global__ void __launch_bounds__(256) k_bgemm3(const float* __restrict__ Wf,
                                                const float* __restrict__ Wbk,
                                                const float* __restrict__ Wd,
                                                const float* __restrict__ bf1, const float* __restrict__ bf2,
                                                const float* __restrict__ bb1, const float* __restrict__ bb2,
                                                const float* __restrict__ bd1, const float* __restrict__ bd2) {
    int mode = blockIdx.z;
    const float* A; const float* W; int ldw; float* C;
    const float *b1, *b2;
    if (mode == 0)      { A = g_embs_src; W = Wf;  ldw = 512;  C = g_Xf; b1 = bf1; b2 = bf2; }
    else if (mode == 1) { A = g_embs_src; W = Wbk; ldw = 512;  C = g_Xb; b1 = bb1; b2 = bb2; }
    else                { A = g_embs_tgt; W = Wd;  ldw = 1024; C = g_Gd; b1 = bd1; b2 = bd2; }
    const int lda = E, ldc = 2048;
    int nb = blockIdx.x, mb = blockIdx.y;
    const float* Ab = A + (size_t)mb * 128 * lda;
    const float* Wb = W + (size_t)nb * 128 * ldw;
    G128_DECL();

    G128_RUN(32);   // K=512

#pragma unroll
    for (int nt = 0; nt < 8; nt++) {
        int n = nb * 128 + no + nt * 8 + 2 * (lane & 3);
        float bv0 = b1[n] + b2[n];
        float bv1 = b1[n + 1] + b2[n + 1];
#pragma unroll
        for (int mt = 0; mt < 2; mt++) {
            int r = mb * 128 + mo + mt * 16 + (lane >> 2);
            C[(size_t)r * ldc + n] = c[mt][nt][0] + bv0;
            C[(size_t)r * ldc + n + 1] = c[mt][nt][1] + bv1;
            C[(size_t)(r + 8) * ldc + n] = c[mt][nt][2] + bv0;
            C[(size_t)(r + 8) * ldc + n + 1] = c[mt][nt][3] + bv1;
        }
    }
}

// ---------------- hs_proj GEMM: g_hsp = g_hs @ Wk^T ----------------
__global__ void __launch_bounds__(256) k_bgemm_hsp(const float* __restrict__ Wk) {
    const int lda = 1024, ldw = 1536, ldc = 1024;
    int nb = blockIdx.x, mb = blockIdx.y;
    const float* Ab = g_hs + (size_t)mb * 128 * lda;
    const float* Wb = Wk + (size_t)nb * 128 * ldw;
    G128_DECL();

    G128_RUN(64);   // K=1024

#pragma unroll
    for (int nt = 0; nt < 8; nt++) {
        int n = nb * 128 + no + nt * 8 + 2 * (lane & 3);
#pragma unroll
        for (int mt = 0; mt < 2; mt++) {
            int r = mb * 128 + mo + mt * 16 + (lane >> 2);
            g_hsp[(size_t)r * ldc + n] = c[mt][nt][0];
            g_hsp[(size_t)r * ldc + n + 1] = c[mt][nt][1];
            g_hsp[(size_t)(r + 8) * ldc + n] = c[mt][nt][2];
            g_hsp[(size_t)(r + 8) * ldc + n + 1] = c[mt][nt][3];
        }
    }
}

// ---------------- tf32 GEMM + fused exp row-sums (output projection) ----------------
__global__ void __launch_bounds__(256) k_lse(const float* __restrict__ oW,
                                             const float* __restrict__ ob) {
    int nb = blockIdx.x, mb = blockIdx.y;
    const int lda = H, ldw = H;
    const float* Ab = g_H + (size_t)mb * 128 * H;
    const float* Wb = oW + (size_t)nb * 128 * H;
    G128_DECL();

    G128_RUN(32);

    float bv0[8], bv1[8];
#pragma unroll
    for (int nt = 0; nt < 8; nt++) {
        int n = nb * 128 + no + nt * 8 + 2 * (lane & 3);
        bv0[nt] = ob[n];
        bv1[nt] = ob[n + 1];
    }
    // reuse stage memory for the row reduction (only empty cp.async groups remain)
    float* red = dsm;   // 128 rows x 8 partials
    __syncthreads();
#pragma unroll
    for (int mt = 0; mt < 2; mt++) {
        float slo = 0.f, shi = 0.f;
#pragma unroll
        for (int nt = 0; nt < 8; nt++) {
            slo += fexp(c[mt][nt][0] + bv0[nt]) + fexp(c[mt][nt][1] + bv1[nt]);
            shi += fexp(c[mt][nt][2] + bv0[nt]) + fexp(c[mt][nt][3] + bv1[nt]);
        }
        int rlo = mo + mt * 16 + (lane >> 2);
        red[rlo * 8 + wn * 4 + (lane & 3)] = slo;
        red[(rlo + 8) * 8 + wn * 4 + (lane & 3)] = shi;
    }
    __syncthreads();
    if (tid < 128) {
        float s = 0.f;
#pragma unroll
        for (int x = 0; x < 8; x++) s += red[tid * 8 + x];
        g_partial[((size_t)mb * 128 + tid) * NCHUNK + nb] = s;
    }
}

// ============================================================================
// cp.async 4-stage pipeline (recurrent kernels, 64xN tiles, K_STEP=32,
// ldmatrix fragment loads — raw fp32 bits, HW tf32 truncation)
// ============================================================================

#define PIPE_IDX()                                                              \
    int tid = threadIdx.x, lane = tid & 31, wid = tid >> 5;                     \
    int mw = wid & 3, nw = wid >> 2;                                            \
    int ar = tid >> 2, aq = tid & 3;                                            \
    int jrow = tid >> 4, jk = tid & 15;                                         \
    int lrow8 = (lane & 7) + (lane & 8);                                        \
    int lcol4 = (lane >> 4) << 2;                                               \
    int pb_bcol4 = ((lane >> 3) & 1) << 2;

#define PIPE_ISSUE_G(S, BUF, CPAA)                                              \
    {                                                                           \
        const float* pa_ = (const float*)srcA(S);                               \
        const float* pb_ = (const float*)srcB(S);                               \
        CPAA(sA + ((BUF) * 64 * PADK2 + ar * PADK2 + aq * 4) * 4, pa_);         \
        CPAA(sA + ((BUF) * 64 * PADK2 + ar * PADK2 + 16 + aq * 4) * 4, pa_ + 16); \
        cpa4(sB + ((BUF) * 16 * PADK2 + jrow * PADK2 + jk) * 4, pb_);           \
        cpa4(sB + ((BUF) * 16 * PADK2 + jrow * PADK2 + 16 + jk) * 4, pb_ + 16); \
    }

#define PIPE_COMPUTE(BUF)                                                       \
    {                                                                           \
        unsigned aab = sA + ((BUF) * 64 * PADK2 + (mw * 16 + lrow8) * PADK2 + lcol4) * 4; \
        unsigned bab = sB + ((BUF) * 16 * PADK2 + (nw * 8 + (lane & 7)) * PADK2 + pb_bcol4) * 4; \
        _Pragma("unroll")                                                       \
        for (int ks = 0; ks < 32; ks += 8) {                                    \
            unsigned a0, a1, a2, a3, b0, b1;                                    \
            ldsm4(a0, a1, a2, a3, aab + ks * 4);                                \
            ldsm2(b0, b1, bab + ks * 4);                                        \
            mma_tf32(acc, a0, a1, a2, a3, b0, b1);                              \
        }                                                                       \
    }

#define PIPE_RUN_G(NS, CPAA)                                                    \
    PIPE_ISSUE_G(0, 0, CPAA); CP_COMMIT();                                      \
    PIPE_ISSUE_G(1, 1, CPAA); CP_COMMIT();                                      \
    PIPE_ISSUE_G(2, 2, CPAA); CP_COMMIT();                                      \
    for (int s = 0; s < (NS); s++) {                                            \
        CP_WAIT2();                                                             \
        __syncthreads();                                                        \
        if (s + 3 < (NS)) PIPE_ISSUE_G(s + 3, (s + 3) & 3, CPAA);               \
        CP_COMMIT();                                                            \
        PIPE_COMPUTE(s & 3);                                                    \
    }                                                                           \
    __syncthreads();

// ---------------- persistent encoder: ONE launch, 256 blocks, 48 steps ----------------
__global__ void __launch_bounds__(256) k_enc_all(const float* __restrict__ Whh_f,
                                                 const float* __restrict__ Whh_b) {
    __shared__ __align__(16) float As[4][64][PADK2];
    __shared__ __align__(16) float Bs[4][16][PADK2];
    __shared__ float gbuf[64][17];
    PIPE_IDX();
    unsigned sA = (unsigned)__cvta_generic_to_shared(&As[0][0][0]);
    unsigned sB = (unsigned)__cvta_generic_to_shared(&Bs[0][0][0]);
    int dir = blockIdx.x >> 7;
    int cu = (blockIdx.x & 127) * 4;
    const float* Whh = dir ? Whh_b : Whh_f;
    int grow = ((jrow >> 2) << 9) + cu + (jrow & 3);

    for (int t = 0; t < LS; t++) {
        const float* hprev; int ldh;
        if (t == 0) { hprev = g_zero; ldh = H; }
        else if (dir == 0) { hprev = g_hs + (size_t)(t - 1) * NB * 1024; ldh = 1024; }
        else { hprev = g_hs + (size_t)(LS - t) * NB * 1024 + 512; ldh = 1024; }

        auto srcA = [&](int s) { return (const void*)&hprev[(size_t)ar * ldh + s * 32 + aq * 4]; };
        auto srcB = [&](int s) { return (const void*)&Whh[(size_t)grow * H + s * 32 + jk]; };

        float acc[4] = {0.f, 0.f, 0.f, 0.f};
        PIPE_RUN_G(16, cpa16);

        {
            int m = mw * 16 + (lane >> 2);
            int n = nw * 8 + 2 * (lane & 3);
            gbuf[m][n] = acc[0]; gbuf[m][n + 1] = acc[1];
            gbuf[m + 8][n] = acc[2]; gbuf[m + 8][n + 1] = acc[3];
        }
        __syncthreads();

        const float* Xg = dir ? (g_Xb + (size_t)(LS - 1 - t) * NB * 2048)
                              : (g_Xf + (size_t)t * NB * 2048);
        float* cst = dir ? g_cb : g_cf;
        float* hs_out = dir ? (g_hs + (size_t)(LS - 1 - t) * NB * 1024 + 512)
                            : (g_hs + (size_t)t * NB * 1024);
        {
            int b = tid & 63, cl = tid >> 6;
            int cell = cu + cl;
            const float* xb = Xg + (size_t)b * 2048;
            float gi = gbuf[b][cl] + xb[cell];
            float gf = gbuf[b][4 + cl] + xb[512 + cell];
            float gg = gbuf[b][8 + cl] + xb[1024 + cell];
            float go = gbuf[b][12 + cl] + xb[1536 + cell];
            float co = cst[b * H + cell];
            float cn = sigm(gf) * co + sigm(gi) * tanhf(gg);
            float hn = sigm(go) * tanhf(cn);
            cst[b * H + cell] = cn;
            hs_out[(size_t)b * 1024 + cell] = hn;
        }
        if (t < LS - 1) {
            __threadfence(); __syncthreads();
            if (tid == 0) st_rel(&g_sE[blockIdx.x], (unsigned)(t + 1));
            { while (ldcg_u32(&g_sE[tid]) < (unsigned)(t + 1)) {} }
            __syncthreads();
        }
    }
}

// ---------------- persistent decoder: ONE launch, 288 blocks, 47 steps x 4 phases ----------------
__global__ void __launch_bounds__(256) k_dec_all(const float* __restrict__ Wih,
                                                 const float* __restrict__ Whh,
                                                 const float* __restrict__ attn_W,
                                                 const float* __restrict__ attn_v,
                                                 const float* __restrict__ lin_W,
                                                 const float* __restrict__ lin_b) {
    __shared__ __align__(16) float As[4][64][PADK2];
    __shared__ __align__(16) float Bs[4][16][PADK2];
    __shared__ float gbuf[64][17];
    PIPE_IDX();
    unsigned sA = (unsigned)__cvta_generic_to_shared(&As[0][0][0]);
    unsigned sB = (unsigned)__cvta_generic_to_shared(&Bs[0][0][0]);
    int blk = blockIdx.x;

    if (blk < 128) {
        // ---- phase 1: gates + LSTM cell ----
        int cu = blk * 4;
        int grow = ((jrow >> 2) << 9) + cu + (jrow & 3);
        for (int t = 0; t < LTm1; t++) {
            const float* hprev = (t == 0) ? g_zero : (g_H + (size_t)(t - 1) * NB * H);
            float acc[4] = {0.f, 0.f, 0.f, 0.f};

            // part 1: h(t-1) @ Whh — needs only peers' g_sH from step t-1
            if (t > 0) WAIT_SLOTS(g_sH, 128, (unsigned)t);
            {
                auto srcA = [&](int s) { return (const void*)&hprev[(size_t)ar * H + s * 32 + aq * 4]; };
                auto srcB = [&](int s) { return (const void*)&Whh[(size_t)grow * H + s * 32 + jk]; };
                PIPE_RUN_G(16, cpa16);
            }
            // part 0: o(t-1) @ Wih[:,512:] — needs o from step t-1
            if (t > 0) WAIT_SLOTS(g_sO, 32, (unsigned)t);
            {
                auto srcA = [&](int s) { return (const void*)&g_od[(size_t)ar * H + s * 32 + aq * 4]; };
                auto srcB = [&](int s) { return (const void*)&Wih[(size_t)grow * 1024 + 512 + s * 32 + jk]; };
                PIPE_RUN_G(16, cpa16cg);
            }

            {
                int m = mw * 16 + (lane >> 2);
                int n = nw * 8 + 2 * (lane & 3);
                gbuf[m][n] = acc[0]; gbuf[m][n + 1] = acc[1];
                gbuf[m + 8][n] = acc[2]; gbuf[m + 8][n + 1] = acc[3];
            }
            __syncthreads();
            {
                int b = tid & 63, cl = tid >> 6;
                int cell = cu + cl;
                const float* xb = g_Gd + (size_t)t * NB * 2048 + (size_t)b * 2048;
                float gi = gbuf[b][cl] + xb[cell];
                float gf = gbuf[b][4 + cl] + xb[512 + cell];
                float gg = gbuf[b][8 + cl] + xb[1024 + cell];
                float go = gbuf[b][12 + cl] + xb[1536 + cell];
                float co = g_cd[b * H + cell];
                float cn = sigm(gf) * co + sigm(gi) * tanhf(gg);
                float hn = sigm(go) * tanhf(cn);
                g_cd[b * H + cell] = cn;
                g_H[((size_t)t * NB + b) * H + cell] = hn;
            }
            ARRIVE_SLOT(g_sH, blk, (unsigned)(t + 1));
        }
    } else if (blk < 192) {
        // ---- phase 2: q = h @ Wq^T ----
        int n0 = (blk - 128) * 16;
        const float* Wr = attn_W + (size_t)(n0 + jrow) * 1536;
        for (int t = 0; t < LTm1; t++) {
            WAIT_SLOTS(g_sH, 128, (unsigned)(t + 1));
            const float* A = g_H + (size_t)t * NB * H;

            auto srcA = [&](int s) { return (const void*)&A[(size_t)ar * H + s * 32 + aq * 4]; };
            auto srcB = [&](int s) { return (const void*)&Wr[s * 32 + jk]; };

            float acc[4] = {0.f, 0.f, 0.f, 0.f};
            PIPE_RUN_G(16, cpa16);

            int m = mw * 16 + (lane >> 2);
            int n = n0 + nw * 8 + 2 * (lane & 3);
            g_q[(size_t)m * 1024 + n] = acc[0];
            g_q[(size_t)m * 1024 + n + 1] = acc[1];
            g_q[(size_t)(m + 8) * 1024 + n] = acc[2];
            g_q[(size_t)(m + 8) * 1024 + n + 1] = acc[3];
            ARRIVE_SLOT(g_sQ, blk - 128, (unsigned)(t + 1));
        }
    } else if (blk < 256) {
        // ---- phase 3: attention ----
        int b = blk - 192;
        float* sq = &As[0][0][0];
        float* sv = &As[0][0][0] + 1024;
        float* sps = &As[0][0][0] + 2048;
        for (int t = 0; t < LTm1; t++) {
            WAIT_SLOTS(g_sQ, 64, (unsigned)(t + 1));
#pragma unroll
            for (int i = 0; i < 4; i++) {
                int k = tid + 256 * i;
                sq[k] = ldcg_f32(&g_q[b * 1024 + k]);
                sv[k] = attn_v[k];
            }
            __syncthreads();
            for (int l = wid; l < LS; l += 8) {
                const float* hp = g_hsp + ((size_t)l * NB + b) * 1024;
                float s = 0.f;
                for (int k = lane; k < 1024; k += 32) s += sv[k] * ftanh(hp[k] + sq[k]);
#pragma unroll
                for (int o = 16; o; o >>= 1) s += __shfl_down_sync(0xffffffff, s, o);
                if (lane == 0) sps[l] = s;
            }
            __syncthreads();
            if (tid < 32) {
                float v0 = (tid < LS) ? sps[tid] : -1e30f;
                float v1 = (tid + 32 < LS) ? sps[tid + 32] : -1e30f;
                float mx = fmaxf(v0, v1);
#pragma unroll
                for (int o = 16; o; o >>= 1) mx = fmaxf(mx, __shfl_xor_sync(0xffffffff, mx, o));
                float e0 = (tid < LS) ? __expf(v0 - mx) : 0.f;
                float e1 = (tid + 32 < LS) ? __expf(v1 - mx) : 0.f;
                float sm = e0 + e1;
#pragma unroll
                for (int o = 16; o; o >>= 1) sm += __shfl_xor_sync(0xffffffff, sm, o);
                float inv = 1.f / sm;
                if (tid < LS) sps[tid] = e0 * inv;
                if (tid + 32 < LS) sps[tid + 32] = e1 * inv;
            }
            __syncthreads();
#pragma unroll
            for (int i = 0; i < 4; i++) {
                int k = tid + 256 * i;
                float acc = 0.f;
                for (int l = 0; l < LS; l++) acc += sps[l] * g_hs[((size_t)l * NB + b) * 1024 + k];
                g_ctx[b * 1024 + k] = acc;
            }
            ARRIVE_SLOT(g_sC, b, (unsigned)(t + 1));
        }
    } else {
        // ---- phase 4: o = tanh([ctx,h] @ lin_W^T + b) ----
        int n0 = (blk - 256) * 16;
        const float* Wr = lin_W + (size_t)(n0 + jrow) * 1536;
        for (int t = 0; t < LTm1; t++) {
            const float* hA = g_H + (size_t)t * NB * H;
            float acc[4] = {0.f, 0.f, 0.f, 0.f};

            // h-part first (cols 1024..1535 of lin_W) — needs only h(t)
            WAIT_SLOTS(g_sH, 128, (unsigned)(t + 1));
            {
                auto srcA = [&](int s) { return (const void*)&hA[(size_t)ar * H + s * 32 + aq * 4]; };
                auto srcB = [&](int s) { return (const void*)&Wr[1024 + s * 32 + jk]; };
                PIPE_RUN_G(16, cpa16);
            }
            // ctx-part (cols 0..1023) — needs attention output
            WAIT_SLOTS(g_sC, 64, (unsigned)(t + 1));
            {
                auto srcA = [&](int s) { return (const void*)&g_ctx[(size_t)ar * 1024 + s * 32 + aq * 4]; };
                auto srcB = [&](int s) { return (const void*)&Wr[s * 32 + jk]; };
                PIPE_RUN_G(32, cpa16cg);
            }

            int m = mw * 16 + (lane >> 2);
            int n = n0 + nw * 8 + 2 * (lane & 3);
            float b0v = lin_b[n], b1v = lin_b[n + 1];
            g_od[(size_t)m * H + n] = tanhf(acc[0] + b0v);
            g_od[(size_t)m * H + n + 1] = tanhf(acc[1] + b1v);
            g_od[(size_t)(m + 8) * H + n] = tanhf(acc[2] + b0v);
            g_od[(size_t)(m + 8) * H + n + 1] = tanhf(acc[3] + b1v);
            ARRIVE_SLOT(g_sO, blk - 256, (unsigned)(t + 1));
        }
    }
}

// ---------------- target logits (one warp per row) ----------------
__global__ void k_tgt(const int* __restrict__ ts, const float* __restrict__ oW,
                      const float* __restrict__ ob) {
    int gw = blockIdx.x * 8 + (threadIdx.x >> 5);
    int lane = threadIdx.x & 31;
    if (gw >= NROWS) return;
    int tok = ts[gw + NB];
    const float* h = g_H + (size_t)gw * H;
    const float* w = oW + (size_t)tok * H;
    float s = 0.f;
    for (int k = lane; k < H; k += 32) s += h[k] * w[k];
#pragma unroll
    for (int o = 16; o; o >>= 1) s += __shfl_down_sync(0xffffffff, s, o);
    if (lane == 0) {
        g_tgt_logit[gw] = s + ob[tok];
        g_maskv[gw] = (tok != 0) ? 1.f : 0.f;
    }
}

// ---------------- final reductions ----------------
__global__ void k_red1() {
    __shared__ float s1[256], s2[256];
    int m = blockIdx.x * 256 + threadIdx.x;
    float v = 0.f, mk = 0.f;
    if (m < NROWS) {
        float s = 0.f;
        const float* p = g_partial + (size_t)m * NCHUNK;
        for (int c = 0; c < NCHUNK; c++) s += p[c];
        mk = g_maskv[m];
        v = (logf(s) - g_tgt_logit[m]) * mk;
    }
    s1[threadIdx.x] = v; s2[threadIdx.x] = mk;
    __syncthreads();
    for (int o = 128; o; o >>= 1) {
        if (threadIdx.x < o) { s1[threadIdx.x] += s1[threadIdx.x + o]; s2[threadIdx.x] += s2[threadIdx.x + o]; }
        __syncthreads();
    }
    if (threadIdx.x == 0) { g_blk[blockIdx.x * 2] = s1[0]; g_blk[blockIdx.x * 2 + 1] = s2[0]; }
}

__global__ void k_red2(float* out) {
    if (threadIdx.x == 0) {
        float a = 0.f, b = 0.f;
        for (int i = 0; i < 12; i++) { a += g_blk[i * 2]; b += g_blk[i * 2 + 1]; }
        out[0] = a / b;
    }
}

// ---------------- launcher ----------------
extern "C" void kernel_launch(void* const* d_in, const int* in_sizes, int n_in,
                              void* d_out, int out_size) {
    const int* xs = (const int*)d_in[0];
    const int* ts = (const int*)d_in[1];
    const float* src_emb = (const float*)d_in[2];
    const float* tgt_emb = (const float*)d_in[3];
    const float* encf_Wih = (const float*)d_in[4];
    const float* encf_Whh = (const float*)d_in[5];
    const float* encf_bih = (const float*)d_in[6];
    const float* encf_bhh = (const float*)d_in[7];
    const float* encb_Wih = (const float*)d_in[8];
    const float* encb_Whh = (const float*)d_in[9];
    const float* encb_bih = (const float*)d_in[10];
    const float* encb_bhh = (const float*)d_in[11];
    const float* dec_Wih = (const float*)d_in[12];
    const float* dec_Whh = (const float*)d_in[13];
    const float* dec_bih = (const float*)d_in[14];
    const float* dec_bhh = (const float*)d_in[15];
    const float* attn_W = (const float*)d_in[16];
    const float* attn_v = (const float*)d_in[17];
    const float* lin_W = (const float*)d_in[18];
    const float* lin_b = (const float*)d_in[19];
    const float* out_W = (const float*)d_in[20];
    const float* out_b = (const float*)d_in[21];

    // raise dynamic smem limit for the G128 family (idempotent, no allocation)
    cudaFuncSetAttribute(k_bgemm3, cudaFuncAttributeMaxDynamicSharedMemorySize, G128_DSMEM);
    cudaFuncSetAttribute(k_bgemm_hsp, cudaFuncAttributeMaxDynamicSharedMemorySize, G128_DSMEM);
    cudaFuncSetAttribute(k_lse, cudaFuncAttributeMaxDynamicSharedMemorySize, G128_DSMEM);

    // init + gathers fused
    k_prep<<<512, 256>>>(xs, ts, src_emb, tgt_emb);

    // precompute GEMMs: 3 modes fused into one launch
    k_bgemm3<<<dim3(16, 24, 3), 256, G128_DSMEM>>>(encf_Wih, encb_Wih, dec_Wih,
                                                   encf_bih, encf_bhh, encb_bih, encb_bhh,
                                                   dec_bih, dec_bhh);

    // encoder: ONE persistent launch (48 steps, slot-flag barrier per step)
    k_enc_all<<<256, 256>>>(encf_Whh, encb_Whh);

    // hs_proj = hs @ Wk^T   (Wk = attn_W[:, 512:], ld 1536)
    k_bgemm_hsp<<<dim3(8, 24), 256, G128_DSMEM>>>(attn_W + 512);

    // decoder: ONE persistent launch (47 steps x 4 phases, slot-flag ring)
    k_dec_all<<<288, 256>>>(dec_Wih, dec_Whh, attn_W, attn_v, lin_W, lin_b);

    // output projection + NLL
    k_tgt<<<376, 256>>>(ts, out_W, out_b);
    k_lse<<<dim3(NCHUNK, NROWS_PAD / 128), 256, G128_DSMEM>>>(out_W, out_b);
    k_red1<<<12, 256>>>();
    k_red2<<<1, 32>>>((float*)d_out);
}

// round 17
// speedup vs baseline: 1.1293x; 1.1293x over previous
#include <cuda_runtime.h>
#include <math.h>

#define LS 48
#define LTm1 47
#define NB 64      // batch
#define E 512
#define H 512
#define VT 32000
#define NROWS 3008      // 47*64 decoder (step,batch) rows
#define NROWS_PAD 3072  // padded to multiple of 128
#define NCHUNK 250      // 32000/128
#define PADK 20         // smem row pad, G128 kernels (16 data + 4 floats)
#define PADK2 36        // smem row pad, PIPE kernels (32 data + 4 floats)
#define PADB 40         // smem row pad, bf16 k_lse (32 data + 8 bf16) = 80B

// ---------------- device scratch (static, allowed) ----------------
__device__ float g_zero[NB * H];
__device__ float g_embs_src[LS * NB * E];
__device__ float g_embs_tgt[NROWS_PAD * E];
__device__ float g_Xf[LS * NB * 2048];
__device__ float g_Xb[LS * NB * 2048];
__device__ float g_Gd[NROWS_PAD * 2048];
__device__ float g_hs[LS * NB * 1024];    // [t][b][1024] fwd||bwd
__device__ float g_hsp[LS * NB * 1024];   // hs_proj [l][b][1024]
__device__ float g_cf[NB * H];
__device__ float g_cb[NB * H];
__device__ float g_cd[NB * H];
__device__ float g_od[NB * H];
__device__ float g_q[NB * 1024];
__device__ float g_ctx[NB * 1024];
__device__ float g_H[NROWS_PAD * H];      // decoder h history (fp32)
__device__ unsigned g_Hb[NROWS_PAD * 256];   // bf16x2-packed g_H
__device__ unsigned g_oWb[VT * 256];         // bf16x2-packed out_W
__device__ float g_tgt_logit[NROWS];
__device__ float g_maskv[NROWS];
__device__ float g_partial[NROWS_PAD * NCHUNK];
__device__ float g_blk[24];
// slot flags: one per producer block, monotonic step values; reset by k_prep
__device__ unsigned g_sE[256], g_sH[128], g_sQ[64], g_sC[64], g_sO[32];

__device__ __forceinline__ float sigm(float x) { return 1.f / (1.f + __expf(-x)); }

__device__ __forceinline__ float ftanh(float x) {
    float y;
    asm("tanh.approx.f32 %0, %1;" : "=f"(y) : "f"(x));
    return y;
}

// fast exp on the FMA pipe
__device__ __forceinline__ float fexp(float x) {
    float y = x * 1.44269504f;
    float fl = floorf(y);
    float f = y - fl;
    float p = fmaf(f, 0.0013333558f, 0.0096181291f);
    p = fmaf(f, p, 0.055504109f);
    p = fmaf(f, p, 0.24022651f);
    p = fmaf(f, p, 0.69314718f);
    p = fmaf(f, p, 1.0f);
    int e = (int)fl;
    return p * __int_as_float((e + 127) << 23);
}

__device__ __forceinline__ void mma_tf32(float* c, unsigned a0, unsigned a1, unsigned a2,
                                         unsigned a3, unsigned b0, unsigned b1) {
    asm volatile(
        "mma.sync.aligned.m16n8k8.row.col.f32.tf32.tf32.f32 "
        "{%0,%1,%2,%3},{%4,%5,%6,%7},{%8,%9},{%0,%1,%2,%3};"
        : "+f"(c[0]), "+f"(c[1]), "+f"(c[2]), "+f"(c[3])
        : "r"(a0), "r"(a1), "r"(a2), "r"(a3), "r"(b0), "r"(b1));
}

__device__ __forceinline__ void mma_bf16(float* c, unsigned a0, unsigned a1, unsigned a2,
                                         unsigned a3, unsigned b0, unsigned b1) {
    asm volatile(
        "mma.sync.aligned.m16n8k16.row.col.f32.bf16.bf16.f32 "
        "{%0,%1,%2,%3},{%4,%5,%6,%7},{%8,%9},{%0,%1,%2,%3};"
        : "+f"(c[0]), "+f"(c[1]), "+f"(c[2]), "+f"(c[3])
        : "r"(a0), "r"(a1), "r"(a2), "r"(a3), "r"(b0), "r"(b1));
}

__device__ __forceinline__ void ldsm4(unsigned& r0, unsigned& r1, unsigned& r2, unsigned& r3,
                                      unsigned addr) {
    asm volatile("ldmatrix.sync.aligned.m8n8.x4.shared.b16 {%0,%1,%2,%3}, [%4];"
                 : "=r"(r0), "=r"(r1), "=r"(r2), "=r"(r3) : "r"(addr));
}
__device__ __forceinline__ void ldsm2(unsigned& r0, unsigned& r1, unsigned addr) {
    asm volatile("ldmatrix.sync.aligned.m8n8.x2.shared.b16 {%0,%1}, [%2];"
                 : "=r"(r0), "=r"(r1) : "r"(addr));
}

__device__ __forceinline__ unsigned pack_bf16(float lo, float hi) {
    unsigned r;
    asm("cvt.rn.bf16x2.f32 %0, %1, %2;" : "=r"(r) : "f"(hi), "f"(lo));
    return r;
}

__device__ __forceinline__ void cpa16(unsigned dst, const void* src) {
    asm volatile("cp.async.ca.shared.global [%0], [%1], 16;" :: "r"(dst), "l"(src) : "memory");
}
__device__ __forceinline__ void cpa16cg(unsigned dst, const void* src) {
    asm volatile("cp.async.cg.shared.global [%0], [%1], 16;" :: "r"(dst), "l"(src) : "memory");
}
__device__ __forceinline__ void cpa4(unsigned dst, const void* src) {
    asm volatile("cp.async.ca.shared.global [%0], [%1], 4;" :: "r"(dst), "l"(src) : "memory");
}
#define CP_COMMIT() asm volatile("cp.async.commit_group;" ::: "memory")
#define CP_WAIT2()  asm volatile("cp.async.wait_group 2;" ::: "memory")
#define CP_WAIT1()  asm volatile("cp.async.wait_group 1;" ::: "memory")

__device__ __forceinline__ unsigned ldcg_u32(const unsigned* p) {
    unsigned v;
    asm volatile("ld.global.cg.u32 %0, [%1];" : "=r"(v) : "l"(p));
    return v;
}
__device__ __forceinline__ float ldcg_f32(const float* p) {
    float v;
    asm volatile("ld.global.cg.f32 %0, [%1];" : "=f"(v) : "l"(p));
    return v;
}
__device__ __forceinline__ void st_rel(unsigned* p, unsigned v) {
    asm volatile("st.global.cg.u32 [%0], %1;" :: "l"(p), "r"(v) : "memory");
}

#define ARRIVE_SLOT(ARR, IDX, V)                                                \
    { __threadfence(); __syncthreads(); if (tid == 0) st_rel(&ARR[IDX], (V)); }
#define WAIT_SLOTS(ARR, CNT, TGT)                                               \
    { if (tid < (CNT)) { while (ldcg_u32(&ARR[tid]) < (TGT)) {} }               \
      __syncthreads(); }

// ---------------- prep: init states + slots + both gathers ----------------
__global__ void k_prep(const int* __restrict__ xs, const int* __restrict__ ts,
                       const float* __restrict__ src_emb, const float* __restrict__ tgt_emb) {
    int i = blockIdx.x * blockDim.x + threadIdx.x;
    int stride = gridDim.x * blockDim.x;
    if (i < 256) {
        g_sE[i] = 0;
        if (i < 128) g_sH[i] = 0;
        if (i < 64) { g_sQ[i] = 0; g_sC[i] = 0; }
        if (i < 32) g_sO[i] = 0;
    }
    int n = NB * H;
    for (int j = i; j < n; j += stride) {
        g_zero[j] = 0.f; g_cf[j] = 0.f; g_cb[j] = 0.f;
        g_cd[j] = 0.f; g_od[j] = 0.f;
        g_H[NROWS * H + j] = 0.f;
        g_embs_tgt[NROWS * E + j] = 0.f;
    }
    const float4* es = (const float4*)src_emb;
    const float4* et = (const float4*)tgt_emb;
    float4* os = (float4*)g_embs_src;
    float4* ot = (float4*)g_embs_tgt;
    int n4s = LS * NB * (E / 4);
    for (int j = i; j < n4s; j += stride) {
        int r = j >> 7, c = j & 127;
        os[j] = es[(size_t)xs[r] * 128 + c];
    }
    int n4t = LTm1 * NB * (E / 4);
    for (int j = i; j < n4t; j += stride) {
        int r = j >> 7, c = j & 127;
        ot[j] = et[(size_t)ts[r] * 128 + c];
    }
}

// ---------------- bf16 conversions ----------------
__global__ void k_cvtW(const float* __restrict__ W) {
    int i = blockIdx.x * blockDim.x + threadIdx.x;
    int n2 = VT * 256;
    const float2* W2 = (const float2*)W;
    for (int j = i; j < n2; j += gridDim.x * blockDim.x) {
        float2 v = W2[j];
        g_oWb[j] = pack_bf16(v.x, v.y);
    }
}

__global__ void k_cvtH() {
    int i = blockIdx.x * blockDim.x + threadIdx.x;
    int n2 = NROWS_PAD * 256;
    const float2* H2 = (const float2*)g_H;
    for (int j = i; j < n2; j += gridDim.x * blockDim.x) {
        float2 v = H2[j];
        g_Hb[j] = pack_bf16(v.x, v.y);
    }
}

// ============================================================================
// 128x128 tf32 GEMM mainloop — 2-stage cp.async, row-major smem [m][PADK],
// ldmatrix fragment loads (raw fp32 bits; HW truncates to tf32).
// ============================================================================

#define G128_DECL()                                                             \
    int tid = threadIdx.x, lane = tid & 31, wid = tid >> 5;                     \
    int wm = wid & 3, wn = wid >> 2;                                            \
    int mo = wm * 32, no = wn * 64;                                             \
    int r0 = tid >> 2, q0 = tid & 3;                                            \
    int lrow8 = (lane & 7) + (lane & 8);                                        \
    int lcol4 = (lane >> 4) << 2;                                               \
    int brow = (lane & 7) + ((lane >> 4) << 3);                                 \
    int bcol4 = ((lane >> 3) & 1) << 2;                                         \
    unsigned sA = (unsigned)__cvta_generic_to_shared(&As[0][0][0]);             \
    unsigned sB = (unsigned)__cvta_generic_to_shared(&Bs[0][0][0]);             \
    float c[2][8][4];                                                           \
    _Pragma("unroll")                                                           \
    for (int mt = 0; mt < 2; mt++)                                              \
        _Pragma("unroll")                                                       \
        for (int nt = 0; nt < 8; nt++)                                          \
            _Pragma("unroll")                                                   \
            for (int j = 0; j < 4; j++) c[mt][nt][j] = 0.f;

#define G128_ISSUE(S, BUF)                                                      \
    {                                                                           \
        cpa16(sA + ((BUF) * 128 * PADK + r0 * PADK + q0 * 4) * 4,               \
              &Ab[(size_t)r0 * lda + (S) * 16 + q0 * 4]);                       \
        cpa16(sA + ((BUF) * 128 * PADK + (r0 + 64) * PADK + q0 * 4) * 4,        \
              &Ab[(size_t)(r0 + 64) * lda + (S) * 16 + q0 * 4]);                \
        cpa16(sB + ((BUF) * 128 * PADK + r0 * PADK + q0 * 4) * 4,               \
              &Wb[(size_t)r0 * ldw + (S) * 16 + q0 * 4]);                       \
        cpa16(sB + ((BUF) * 128 * PADK + (r0 + 64) * PADK + q0 * 4) * 4,        \
              &Wb[(size_t)(r0 + 64) * ldw + (S) * 16 + q0 * 4]);                \
    }

#define G128_COMPUTE(BUF)                                                       \
    _Pragma("unroll")                                                           \
    for (int ks = 0; ks < 16; ks += 8) {                                        \
        unsigned a[2][4];                                                       \
        _Pragma("unroll")                                                       \
        for (int mt = 0; mt < 2; mt++) {                                        \
            unsigned ad = sA + ((BUF) * 128 * PADK +                            \
                                (mo + mt * 16 + lrow8) * PADK + ks + lcol4) * 4;\
            ldsm4(a[mt][0], a[mt][1], a[mt][2], a[mt][3], ad);                  \
        }                                                                       \
        _Pragma("unroll")                                                       \
        for (int np = 0; np < 4; np++) {                                        \
            unsigned b0, b1, b2, b3;                                            \
            unsigned bd = sB + ((BUF) * 128 * PADK +                            \
                                (no + np * 16 + brow) * PADK + ks + bcol4) * 4; \
            ldsm4(b0, b1, b2, b3, bd);                                          \
            mma_tf32(c[0][np * 2], a[0][0], a[0][1], a[0][2], a[0][3], b0, b1); \
            mma_tf32(c[1][np * 2], a[1][0], a[1][1], a[1][2], a[1][3], b0, b1); \
            mma_tf32(c[0][np * 2 + 1], a[0][0], a[0][1], a[0][2], a[0][3], b2, b3); \
            mma_tf32(c[1][np * 2 + 1], a[1][0], a[1][1], a[1][2], a[1][3], b2, b3); \
        }                                                                       \
    }

#define G128_RUN(NS)                                                            \
    G128_ISSUE(0, 0); CP_COMMIT();                                              \
    G128_ISSUE(1, 1); CP_COMMIT();                                              \
    for (int s = 0; s < (NS); s++) {                                            \
        CP_WAIT1();                                                             \
        __syncthreads();                                                        \
        G128_COMPUTE(s & 1);                                                    \
        __syncthreads();                                                        \
        if (s + 2 < (NS)) G128_ISSUE(s + 2, s & 1);                             \
        CP_COMMIT();                                                            \
    }

// ---------------- fused precompute GEMMs: 3 modes in one launch (grid.z) ----------------
__global__ void __launch_bounds__(256) k_bgemm3(const float* __restrict__ Wf,
                                                const float* __restrict__ Wbk,
                                                const float* __restrict__ Wd,
                                                const float* __restrict__ bf1, const float* __restrict__ bf2,
                                                const float* __restrict__ bb1, const float* __restrict__ bb2,
                                                const float* __restrict__ bd1, const float* __restrict__ bd2) {
    __shared__ __align__(16) float As[2][128][PADK];
    __shared__ __align__(16) float Bs[2][128][PADK];
    int mode = blockIdx.z;
    const float* A; const float* W; int ldw; float* C;
    const float *b1, *b2;
    if (mode == 0)      { A = g_embs_src; W = Wf;  ldw = 512;  C = g_Xf; b1 = bf1; b2 = bf2; }
    else if (mode == 1) { A = g_embs_src; W = Wbk; ldw = 512;  C = g_Xb; b1 = bb1; b2 = bb2; }
    else                { A = g_embs_tgt; W = Wd;  ldw = 1024; C = g_Gd; b1 = bd1; b2 = bd2; }
    const int lda = E, ldc = 2048;
    int nb = blockIdx.x, mb = blockIdx.y;
    const float* Ab = A + (size_t)mb * 128 * lda;
    const float* Wb = W + (size_t)nb * 128 * ldw;
    G128_DECL();

    G128_RUN(32);   // K=512

#pragma unroll
    for (int nt = 0; nt < 8; nt++) {
        int n = nb * 128 + no + nt * 8 + 2 * (lane & 3);
        float bv0 = b1[n] + b2[n];
        float bv1 = b1[n + 1] + b2[n + 1];
#pragma unroll
        for (int mt = 0; mt < 2; mt++) {
            int r = mb * 128 + mo + mt * 16 + (lane >> 2);
            C[(size_t)r * ldc + n] = c[mt][nt][0] + bv0;
            C[(size_t)r * ldc + n + 1] = c[mt][nt][1] + bv1;
            C[(size_t)(r + 8) * ldc + n] = c[mt][nt][2] + bv0;
            C[(size_t)(r + 8) * ldc + n + 1] = c[mt][nt][3] + bv1;
        }
    }
}

// ---------------- hs_proj GEMM: g_hsp = g_hs @ Wk^T ----------------
__global__ void __launch_bounds__(256) k_bgemm_hsp(const float* __restrict__ Wk) {
    __shared__ __align__(16) float As[2][128][PADK];
    __shared__ __align__(16) float Bs[2][128][PADK];
    const int lda = 1024, ldw = 1536, ldc = 1024;
    int nb = blockIdx.x, mb = blockIdx.y;
    const float* Ab = g_hs + (size_t)mb * 128 * lda;
    const float* Wb = Wk + (size_t)nb * 128 * ldw;
    G128_DECL();

    G128_RUN(64);   // K=1024

#pragma unroll
    for (int nt = 0; nt < 8; nt++) {
        int n = nb * 128 + no + nt * 8 + 2 * (lane & 3);
#pragma unroll
        for (int mt = 0; mt < 2; mt++) {
            int r = mb * 128 + mo + mt * 16 + (lane >> 2);
            g_hsp[(size_t)r * ldc + n] = c[mt][nt][0];
            g_hsp[(size_t)r * ldc + n + 1] = c[mt][nt][1];
            g_hsp[(size_t)(r + 8) * ldc + n] = c[mt][nt][2];
            g_hsp[(size_t)(r + 8) * ldc + n + 1] = c[mt][nt][3];
        }
    }
}

// ---------------- bf16 GEMM + fused exp row-sums (output projection) ----------------
// A = g_Hb [3072][512] bf16, B = g_oWb [32000][512] bf16; K stage = 32 bf16/row.
__global__ void __launch_bounds__(256) k_lse(const float* __restrict__ ob) {
    __shared__ __align__(16) unsigned short As[2][128][PADB];
    __shared__ __align__(16) unsigned short Bs[2][128][PADB];
    __shared__ float red[128][8];
    int nb = blockIdx.x, mb = blockIdx.y;
    int tid = threadIdx.x, lane = tid & 31, wid = tid >> 5;
    int wm = wid & 3, wn = wid >> 2;
    int mo = wm * 32, no = wn * 64;
    int cr0 = tid >> 2, cq0 = tid & 3;            // 16B-chunk loader: row, chunk-in-row
    int lrow8 = (lane & 7) + (lane & 8);
    int lcolB = (lane >> 4) << 3;                 // bf16 units (k offset 0/8)
    int browB = (lane & 7) + ((lane >> 4) << 3);
    int bcolB = ((lane >> 3) & 1) << 3;
    unsigned sA = (unsigned)__cvta_generic_to_shared(&As[0][0][0]);
    unsigned sB = (unsigned)__cvta_generic_to_shared(&Bs[0][0][0]);

    float c[2][8][4];
#pragma unroll
    for (int mt = 0; mt < 2; mt++)
#pragma unroll
        for (int nt = 0; nt < 8; nt++)
#pragma unroll
            for (int j = 0; j < 4; j++) c[mt][nt][j] = 0.f;

    // stage S covers k [S*32, S*32+32) bf16 = 16 packed unsigned per row
#define LSE_ISSUE(S, BUF)                                                       \
    {                                                                           \
        cpa16(sA + ((BUF) * 128 * PADB + cr0 * PADB + cq0 * 8) * 2,             \
              &g_Hb[(size_t)(mb * 128 + cr0) * 256 + (S) * 16 + cq0 * 4]);      \
        cpa16(sA + ((BUF) * 128 * PADB + (cr0 + 64) * PADB + cq0 * 8) * 2,      \
              &g_Hb[(size_t)(mb * 128 + cr0 + 64) * 256 + (S) * 16 + cq0 * 4]); \
        cpa16(sB + ((BUF) * 128 * PADB + cr0 * PADB + cq0 * 8) * 2,             \
              &g_oWb[(size_t)(nb * 128 + cr0) * 256 + (S) * 16 + cq0 * 4]);     \
        cpa16(sB + ((BUF) * 128 * PADB + (cr0 + 64) * PADB + cq0 * 8) * 2,      \
              &g_oWb[(size_t)(nb * 128 + cr0 + 64) * 256 + (S) * 16 + cq0 * 4]);\
    }

#define LSE_COMPUTE(BUF)                                                        \
    _Pragma("unroll")                                                           \
    for (int ks = 0; ks < 32; ks += 16) {                                       \
        unsigned a[2][4];                                                       \
        _Pragma("unroll")                                                       \
        for (int mt = 0; mt < 2; mt++) {                                        \
            unsigned ad = sA + ((BUF) * 128 * PADB +                            \
                                (mo + mt * 16 + lrow8) * PADB + ks + lcolB) * 2;\
            ldsm4(a[mt][0], a[mt][1], a[mt][2], a[mt][3], ad);                  \
        }                                                                       \
        _Pragma("unroll")                                                       \
        for (int np = 0; np < 4; np++) {                                        \
            unsigned b0, b1, b2, b3;                                            \
            unsigned bd = sB + ((BUF) * 128 * PADB +                            \
                                (no + np * 16 + browB) * PADB + ks + bcolB) * 2;\
            ldsm4(b0, b1, b2, b3, bd);                                          \
            mma_bf16(c[0][np * 2], a[0][0], a[0][1], a[0][2], a[0][3], b0, b1); \
            mma_bf16(c[1][np * 2], a[1][0], a[1][1], a[1][2], a[1][3], b0, b1); \
            mma_bf16(c[0][np * 2 + 1], a[0][0], a[0][1], a[0][2], a[0][3], b2, b3); \
            mma_bf16(c[1][np * 2 + 1], a[1][0], a[1][1], a[1][2], a[1][3], b2, b3); \
        }                                                                       \
    }

    LSE_ISSUE(0, 0); CP_COMMIT();
    LSE_ISSUE(1, 1); CP_COMMIT();
    for (int s = 0; s < 16; s++) {          // K=512 / 32
        CP_WAIT1();
        __syncthreads();
        LSE_COMPUTE(s & 1);
        __syncthreads();
        if (s + 2 < 16) LSE_ISSUE(s + 2, s & 1);
        CP_COMMIT();
    }

    float bv0[8], bv1[8];
#pragma unroll
    for (int nt = 0; nt < 8; nt++) {
        int n = nb * 128 + no + nt * 8 + 2 * (lane & 3);
        bv0[nt] = ob[n];
        bv1[nt] = ob[n + 1];
    }
    __syncthreads();
#pragma unroll
    for (int mt = 0; mt < 2; mt++) {
        float slo = 0.f, shi = 0.f;
#pragma unroll
        for (int nt = 0; nt < 8; nt++) {
            slo += fexp(c[mt][nt][0] + bv0[nt]) + fexp(c[mt][nt][1] + bv1[nt]);
            shi += fexp(c[mt][nt][2] + bv0[nt]) + fexp(c[mt][nt][3] + bv1[nt]);
        }
        int rlo = mo + mt * 16 + (lane >> 2);
        red[rlo][wn * 4 + (lane & 3)] = slo;
        red[rlo + 8][wn * 4 + (lane & 3)] = shi;
    }
    __syncthreads();
    if (tid < 128) {
        float s = 0.f;
#pragma unroll
        for (int x = 0; x < 8; x++) s += red[tid][x];
        g_partial[((size_t)mb * 128 + tid) * NCHUNK + nb] = s;
    }
}

// ============================================================================
// cp.async 4-stage pipeline (recurrent kernels, 64xN tiles, K_STEP=32,
// ldmatrix fragment loads — raw fp32 bits, HW tf32 truncation)
// ============================================================================

#define PIPE_IDX()                                                              \
    int tid = threadIdx.x, lane = tid & 31, wid = tid >> 5;                     \
    int mw = wid & 3, nw = wid >> 2;                                            \
    int ar = tid >> 2, aq = tid & 3;                                            \
    int jrow = tid >> 4, jk = tid & 15;                                         \
    int lrow8 = (lane & 7) + (lane & 8);                                        \
    int lcol4 = (lane >> 4) << 2;                                               \
    int pb_bcol4 = ((lane >> 3) & 1) << 2;

#define PIPE_ISSUE_G(S, BUF, CPAA)                                              \
    {                                                                           \
        const float* pa_ = (const float*)srcA(S);                               \
        const float* pb_ = (const float*)srcB(S);                               \
        CPAA(sA + ((BUF) * 64 * PADK2 + ar * PADK2 + aq * 4) * 4, pa_);         \
        CPAA(sA + ((BUF) * 64 * PADK2 + ar * PADK2 + 16 + aq * 4) * 4, pa_ + 16); \
        cpa4(sB + ((BUF) * 16 * PADK2 + jrow * PADK2 + jk) * 4, pb_);           \
        cpa4(sB + ((BUF) * 16 * PADK2 + jrow * PADK2 + 16 + jk) * 4, pb_ + 16); \
    }

#define PIPE_COMPUTE(BUF)                                                       \
    {                                                                           \
        unsigned aab = sA + ((BUF) * 64 * PADK2 + (mw * 16 + lrow8) * PADK2 + lcol4) * 4; \
        unsigned bab = sB + ((BUF) * 16 * PADK2 + (nw * 8 + (lane & 7)) * PADK2 + pb_bcol4) * 4; \
        _Pragma("unroll")                                                       \
        for (int ks = 0; ks < 32; ks += 8) {                                    \
            unsigned a0, a1, a2, a3, b0, b1;                                    \
            ldsm4(a0, a1, a2, a3, aab + ks * 4);                                \
            ldsm2(b0, b1, bab + ks * 4);                                        \
            mma_tf32(acc, a0, a1, a2, a3, b0, b1);                              \
        }                                                                       \
    }

#define PIPE_RUN_G(NS, CPAA)                                                    \
    PIPE_ISSUE_G(0, 0, CPAA); CP_COMMIT();                                      \
    PIPE_ISSUE_G(1, 1, CPAA); CP_COMMIT();                                      \
    PIPE_ISSUE_G(2, 2, CPAA); CP_COMMIT();                                      \
    for (int s = 0; s < (NS); s++) {                                            \
        CP_WAIT2();                                                             \
        __syncthreads();                                                        \
        if (s + 3 < (NS)) PIPE_ISSUE_G(s + 3, (s + 3) & 3, CPAA);               \
        CP_COMMIT();                                                            \
        PIPE_COMPUTE(s & 3);                                                    \
    }                                                                           \
    __syncthreads();

// ---------------- persistent encoder: ONE launch, 256 blocks, 48 steps ----------------
__global__ void __launch_bounds__(256) k_enc_all(const float* __restrict__ Whh_f,
                                                 const float* __restrict__ Whh_b) {
    __shared__ __align__(16) float As[4][64][PADK2];
    __shared__ __align__(16) float Bs[4][16][PADK2];
    __shared__ float gbuf[64][17];
    PIPE_IDX();
    unsigned sA = (unsigned)__cvta_generic_to_shared(&As[0][0][0]);
    unsigned sB = (unsigned)__cvta_generic_to_shared(&Bs[0][0][0]);
    int dir = blockIdx.x >> 7;
    int cu = (blockIdx.x & 127) * 4;
    const float* Whh = dir ? Whh_b : Whh_f;
    int grow = ((jrow >> 2) << 9) + cu + (jrow & 3);

    for (int t = 0; t < LS; t++) {
        const float* hprev; int ldh;
        if (t == 0) { hprev = g_zero; ldh = H; }
        else if (dir == 0) { hprev = g_hs + (size_t)(t - 1) * NB * 1024; ldh = 1024; }
        else { hprev = g_hs + (size_t)(LS - t) * NB * 1024 + 512; ldh = 1024; }

        auto srcA = [&](int s) { return (const void*)&hprev[(size_t)ar * ldh + s * 32 + aq * 4]; };
        auto srcB = [&](int s) { return (const void*)&Whh[(size_t)grow * H + s * 32 + jk]; };

        float acc[4] = {0.f, 0.f, 0.f, 0.f};
        PIPE_RUN_G(16, cpa16);

        {
            int m = mw * 16 + (lane >> 2);
            int n = nw * 8 + 2 * (lane & 3);
            gbuf[m][n] = acc[0]; gbuf[m][n + 1] = acc[1];
            gbuf[m + 8][n] = acc[2]; gbuf[m + 8][n + 1] = acc[3];
        }
        __syncthreads();

        const float* Xg = dir ? (g_Xb + (size_t)(LS - 1 - t) * NB * 2048)
                              : (g_Xf + (size_t)t * NB * 2048);
        float* cst = dir ? g_cb : g_cf;
        float* hs_out = dir ? (g_hs + (size_t)(LS - 1 - t) * NB * 1024 + 512)
                            : (g_hs + (size_t)t * NB * 1024);
        {
            int b = tid & 63, cl = tid >> 6;
            int cell = cu + cl;
            const float* xb = Xg + (size_t)b * 2048;
            float gi = gbuf[b][cl] + xb[cell];
            float gf = gbuf[b][4 + cl] + xb[512 + cell];
            float gg = gbuf[b][8 + cl] + xb[1024 + cell];
            float go = gbuf[b][12 + cl] + xb[1536 + cell];
            float co = cst[b * H + cell];
            float cn = sigm(gf) * co + sigm(gi) * tanhf(gg);
            float hn = sigm(go) * tanhf(cn);
            cst[b * H + cell] = cn;
            hs_out[(size_t)b * 1024 + cell] = hn;
        }
        if (t < LS - 1) {
            __threadfence(); __syncthreads();
            if (tid == 0) st_rel(&g_sE[blockIdx.x], (unsigned)(t + 1));
            { while (ldcg_u32(&g_sE[tid]) < (unsigned)(t + 1)) {} }
            __syncthreads();
        }
    }
}

// ---------------- persistent decoder: ONE launch, 288 blocks, 47 steps x 4 phases ----------------
__global__ void __launch_bounds__(256) k_dec_all(const float* __restrict__ Wih,
                                                 const float* __restrict__ Whh,
                                                 const float* __restrict__ attn_W,
                                                 const float* __restrict__ attn_v,
                                                 const float* __restrict__ lin_W,
                                                 const float* __restrict__ lin_b) {
    __shared__ __align__(16) float As[4][64][PADK2];
    __shared__ __align__(16) float Bs[4][16][PADK2];
    __shared__ float gbuf[64][17];
    PIPE_IDX();
    unsigned sA = (unsigned)__cvta_generic_to_shared(&As[0][0][0]);
    unsigned sB = (unsigned)__cvta_generic_to_shared(&Bs[0][0][0]);
    int blk = blockIdx.x;

    if (blk < 128) {
        // ---- phase 1: gates + LSTM cell ----
        int cu = blk * 4;
        int grow = ((jrow >> 2) << 9) + cu + (jrow & 3);
        for (int t = 0; t < LTm1; t++) {
            const float* hprev = (t == 0) ? g_zero : (g_H + (size_t)(t - 1) * NB * H);
            float acc[4] = {0.f, 0.f, 0.f, 0.f};

            if (t > 0) WAIT_SLOTS(g_sH, 128, (unsigned)t);
            {
                auto srcA = [&](int s) { return (const void*)&hprev[(size_t)ar * H + s * 32 + aq * 4]; };
                auto srcB = [&](int s) { return (const void*)&Whh[(size_t)grow * H + s * 32 + jk]; };
                PIPE_RUN_G(16, cpa16);
            }
            if (t > 0) WAIT_SLOTS(g_sO, 32, (unsigned)t);
            {
                auto srcA = [&](int s) { return (const void*)&g_od[(size_t)ar * H + s * 32 + aq * 4]; };
                auto srcB = [&](int s) { return (const void*)&Wih[(size_t)grow * 1024 + 512 + s * 32 + jk]; };
                PIPE_RUN_G(16, cpa16cg);
            }

            {
                int m = mw * 16 + (lane >> 2);
                int n = nw * 8 + 2 * (lane & 3);
                gbuf[m][n] = acc[0]; gbuf[m][n + 1] = acc[1];
                gbuf[m + 8][n] = acc[2]; gbuf[m + 8][n + 1] = acc[3];
            }
            __syncthreads();
            {
                int b = tid & 63, cl = tid >> 6;
                int cell = cu + cl;
                const float* xb = g_Gd + (size_t)t * NB * 2048 + (size_t)b * 2048;
                float gi = gbuf[b][cl] + xb[cell];
                float gf = gbuf[b][4 + cl] + xb[512 + cell];
                float gg = gbuf[b][8 + cl] + xb[1024 + cell];
                float go = gbuf[b][12 + cl] + xb[1536 + cell];
                float co = g_cd[b * H + cell];
                float cn = sigm(gf) * co + sigm(gi) * tanhf(gg);
                float hn = sigm(go) * tanhf(cn);
                g_cd[b * H + cell] = cn;
                g_H[((size_t)t * NB + b) * H + cell] = hn;
            }
            ARRIVE_SLOT(g_sH, blk, (unsigned)(t + 1));
        }
    } else if (blk < 192) {
        // ---- phase 2: q = h @ Wq^T ----
        int n0 = (blk - 128) * 16;
        const float* Wr = attn_W + (size_t)(n0 + jrow) * 1536;
        for (int t = 0; t < LTm1; t++) {
            WAIT_SLOTS(g_sH, 128, (unsigned)(t + 1));
            const float* A = g_H + (size_t)t * NB * H;

            auto srcA = [&](int s) { return (const void*)&A[(size_t)ar * H + s * 32 + aq * 4]; };
            auto srcB = [&](int s) { return (const void*)&Wr[s * 32 + jk]; };

            float acc[4] = {0.f, 0.f, 0.f, 0.f};
            PIPE_RUN_G(16, cpa16);

            int m = mw * 16 + (lane >> 2);
            int n = n0 + nw * 8 + 2 * (lane & 3);
            g_q[(size_t)m * 1024 + n] = acc[0];
            g_q[(size_t)m * 1024 + n + 1] = acc[1];
            g_q[(size_t)(m + 8) * 1024 + n] = acc[2];
            g_q[(size_t)(m + 8) * 1024 + n + 1] = acc[3];
            ARRIVE_SLOT(g_sQ, blk - 128, (unsigned)(t + 1));
        }
    } else if (blk < 256) {
        // ---- phase 3: attention ----
        int b = blk - 192;
        float* sq = (float*)&As[0][0][0];
        float* sv = (float*)&As[0][0][0] + 1024;
        float* sps = (float*)&As[0][0][0] + 2048;
        for (int t = 0; t < LTm1; t++) {
            WAIT_SLOTS(g_sQ, 64, (unsigned)(t + 1));
#pragma unroll
            for (int i = 0; i < 4; i++) {
                int k = tid + 256 * i;
                sq[k] = ldcg_f32(&g_q[b * 1024 + k]);
                sv[k] = attn_v[k];
            }
            __syncthreads();
            for (int l = wid; l < LS; l += 8) {
                const float* hp = g_hsp + ((size_t)l * NB + b) * 1024;
                float s = 0.f;
                for (int k = lane; k < 1024; k += 32) s += sv[k] * ftanh(hp[k] + sq[k]);
#pragma unroll
                for (int o = 16; o; o >>= 1) s += __shfl_down_sync(0xffffffff, s, o);
                if (lane == 0) sps[l] = s;
            }
            __syncthreads();
            if (tid < 32) {
                float v0 = (tid < LS) ? sps[tid] : -1e30f;
                float v1 = (tid + 32 < LS) ? sps[tid + 32] : -1e30f;
                float mx = fmaxf(v0, v1);
#pragma unroll
                for (int o = 16; o; o >>= 1) mx = fmaxf(mx, __shfl_xor_sync(0xffffffff, mx, o));
                float e0 = (tid < LS) ? __expf(v0 - mx) : 0.f;
                float e1 = (tid + 32 < LS) ? __expf(v1 - mx) : 0.f;
                float sm = e0 + e1;
#pragma unroll
                for (int o = 16; o; o >>= 1) sm += __shfl_xor_sync(0xffffffff, sm, o);
                float inv = 1.f / sm;
                if (tid < LS) sps[tid] = e0 * inv;
                if (tid + 32 < LS) sps[tid + 32] = e1 * inv;
            }
            __syncthreads();
#pragma unroll
            for (int i = 0; i < 4; i++) {
                int k = tid + 256 * i;
                float acc = 0.f;
                for (int l = 0; l < LS; l++) acc += sps[l] * g_hs[((size_t)l * NB + b) * 1024 + k];
                g_ctx[b * 1024 + k] = acc;
            }
            ARRIVE_SLOT(g_sC, b, (unsigned)(t + 1));
        }
    } else {
        // ---- phase 4: o = tanh([ctx,h] @ lin_W^T + b) ----
        int n0 = (blk - 256) * 16;
        const float* Wr = lin_W + (size_t)(n0 + jrow) * 1536;
        for (int t = 0; t < LTm1; t++) {
            const float* hA = g_H + (size_t)t * NB * H;
            float acc[4] = {0.f, 0.f, 0.f, 0.f};

            WAIT_SLOTS(g_sH, 128, (unsigned)(t + 1));
            {
                auto srcA = [&](int s) { return (const void*)&hA[(size_t)ar * H + s * 32 + aq * 4]; };
                auto srcB = [&](int s) { return (const void*)&Wr[1024 + s * 32 + jk]; };
                PIPE_RUN_G(16, cpa16);
            }
            WAIT_SLOTS(g_sC, 64, (unsigned)(t + 1));
            {
                auto srcA = [&](int s) { return (const void*)&g_ctx[(size_t)ar * 1024 + s * 32 + aq * 4]; };
                auto srcB = [&](int s) { return (const void*)&Wr[s * 32 + jk]; };
                PIPE_RUN_G(32, cpa16cg);
            }

            int m = mw * 16 + (lane >> 2);
            int n = n0 + nw * 8 + 2 * (lane & 3);
            float b0v = lin_b[n], b1v = lin_b[n + 1];
            g_od[(size_t)m * H + n] = tanhf(acc[0] + b0v);
            g_od[(size_t)m * H + n + 1] = tanhf(acc[1] + b1v);
            g_od[(size_t)(m + 8) * H + n] = tanhf(acc[2] + b0v);
            g_od[(size_t)(m + 8) * H + n + 1] = tanhf(acc[3] + b1v);
            ARRIVE_SLOT(g_sO, blk - 256, (unsigned)(t + 1));
        }
    }
}

// ---------------- target logits (one warp per row, fp32 — exact path) ----------------
__global__ void k_tgt(const int* __restrict__ ts, const float* __restrict__ oW,
                      const float* __restrict__ ob) {
    int gw = blockIdx.x * 8 + (threadIdx.x >> 5);
    int lane = threadIdx.x & 31;
    if (gw >= NROWS) return;
    int tok = ts[gw + NB];
    const float* h = g_H + (size_t)gw * H;
    const float* w = oW + (size_t)tok * H;
    float s = 0.f;
    for (int k = lane; k < H; k += 32) s += h[k] * w[k];
#pragma unroll
    for (int o = 16; o; o >>= 1) s += __shfl_down_sync(0xffffffff, s, o);
    if (lane == 0) {
        g_tgt_logit[gw] = s + ob[tok];
        g_maskv[gw] = (tok != 0) ? 1.f : 0.f;
    }
}

// ---------------- final reductions ----------------
__global__ void k_red1() {
    __shared__ float s1[256], s2[256];
    int m = blockIdx.x * 256 + threadIdx.x;
    float v = 0.f, mk = 0.f;
    if (m < NROWS) {
        float s = 0.f;
        const float* p = g_partial + (size_t)m * NCHUNK;
        for (int c = 0; c < NCHUNK; c++) s += p[c];
        mk = g_maskv[m];
        v = (logf(s) - g_tgt_logit[m]) * mk;
    }
    s1[threadIdx.x] = v; s2[threadIdx.x] = mk;
    __syncthreads();
    for (int o = 128; o; o >>= 1) {
        if (threadIdx.x < o) { s1[threadIdx.x] += s1[threadIdx.x + o]; s2[threadIdx.x] += s2[threadIdx.x + o]; }
        __syncthreads();
    }
    if (threadIdx.x == 0) { g_blk[blockIdx.x * 2] = s1[0]; g_blk[blockIdx.x * 2 + 1] = s2[0]; }
}

__global__ void k_red2(float* out) {
    if (threadIdx.x == 0) {
        float a = 0.f, b = 0.f;
        for (int i = 0; i < 12; i++) { a += g_blk[i * 2]; b += g_blk[i * 2 + 1]; }
        out[0] = a / b;
    }
}

// ---------------- launcher ----------------
extern "C" void kernel_launch(void* const* d_in, const int* in_sizes, int n_in,
                              void* d_out, int out_size) {
    const int* xs = (const int*)d_in[0];
    const int* ts = (const int*)d_in[1];
    const float* src_emb = (const float*)d_in[2];
    const float* tgt_emb = (const float*)d_in[3];
    const float* encf_Wih = (const float*)d_in[4];
    const float* encf_Whh = (const float*)d_in[5];
    const float* encf_bih = (const float*)d_in[6];
    const float* encf_bhh = (const float*)d_in[7];
    const float* encb_Wih = (const float*)d_in[8];
    const float* encb_Whh = (const float*)d_in[9];
    const float* encb_bih = (const float*)d_in[10];
    const float* encb_bhh = (const float*)d_in[11];
    const float* dec_Wih = (const float*)d_in[12];
    const float* dec_Whh = (const float*)d_in[13];
    const float* dec_bih = (const float*)d_in[14];
    const float* dec_bhh = (const float*)d_in[15];
    const float* attn_W = (const float*)d_in[16];
    const float* attn_v = (const float*)d_in[17];
    const float* lin_W = (const float*)d_in[18];
    const float* lin_b = (const float*)d_in[19];
    const float* out_W = (const float*)d_in[20];
    const float* out_b = (const float*)d_in[21];

    // init + gathers fused
    k_prep<<<512, 256>>>(xs, ts, src_emb, tgt_emb);

    // out_W -> bf16 (independent of everything else; runs early, off critical path)
    k_cvtW<<<2048, 256>>>(out_W);

    // precompute GEMMs: 3 modes fused into one launch
    k_bgemm3<<<dim3(16, 24, 3), 256>>>(encf_Wih, encb_Wih, dec_Wih,
                                       encf_bih, encf_bhh, encb_bih, encb_bhh,
                                       dec_bih, dec_bhh);

    // encoder: ONE persistent launch (48 steps, slot-flag barrier per step)
    k_enc_all<<<256, 256>>>(encf_Whh, encb_Whh);

    // hs_proj = hs @ Wk^T   (Wk = attn_W[:, 512:], ld 1536)
    k_bgemm_hsp<<<dim3(8, 24), 256>>>(attn_W + 512);

    // decoder: ONE persistent launch (47 steps x 4 phases, slot-flag ring)
    k_dec_all<<<288, 256>>>(dec_Wih, dec_Whh, attn_W, attn_v, lin_W, lin_b);

    // g_H -> bf16, then output projection + NLL
    k_cvtH<<<512, 256>>>();
    k_tgt<<<376, 256>>>(ts, out_W, out_b);
    k_lse<<<dim3(NCHUNK, NROWS_PAD / 128), 256>>>(out_b);
    k_red1<<<12, 256>>>();
    k_red2<<<1, 32>>>((float*)d_out);
}